// round 10
// baseline (speedup 1.0000x reference)
#include <cuda_runtime.h>
#include <cuda_fp16.h>
#include <cstdint>
#include <cstddef>

#define BSZ   8192
#define DIMN  100
#define NSTEP 49
#define WH    256
#define RRATE 0.05f
#define KP1   112

// ---------------- device scratch (static, no allocations) ----------------
__device__ float g_volpre[(size_t)NSTEP * BSZ * DIMN]; // 160.6 MB
__device__ float g_Sbuf[2][BSZ * DIMN];
__device__ float g_grad[BSZ * DIMN];
__device__ float g_vbuf[2][BSZ];
__device__ float g_stoch[BSZ];
__device__ float g_err[BSZ];
// packed activations: interleaved hi/lo, [row][kg][hl] x 16B units; row stride = KG*16 halves
__device__ __align__(16) __half g_actA[(size_t)2 * BSZ * WH * 2];   // 16 MB
__device__ __align__(16) __half g_actB[(size_t)2 * BSZ * WH * 2];
// packed weights (pre-transposed [n][k], pre-split, interleaved)
__device__ __align__(16) __half g_Win_pk[2][WH * KP1 * 2];
__device__ __align__(16) __half g_Wh_pk[2][3 * WH * WH * 2];
__device__ __align__(16) __half g_Wout_pk[128 * WH * 2];
__device__ __align__(16) __half g_V_pk[128 * KP1 * 2];

// ---------------- helpers ----------------
__device__ __forceinline__ uint32_t smem_u32(const void* p) {
    uint32_t a;
    asm("{ .reg .u64 t; cvta.to.shared.u64 t, %1; cvt.u32.u64 %0, t; }" : "=r"(a) : "l"(p));
    return a;
}
__device__ __forceinline__ void split2(float x0, float x1, uint32_t& h, uint32_t& l) {
    __half2 hh = __floats2half2_rn(x0, x1);
    float2 hf = __half22float2(hh);
    __half2 ll = __floats2half2_rn(x0 - hf.x, x1 - hf.y);
    h = *reinterpret_cast<uint32_t*>(&hh);
    l = *reinterpret_cast<uint32_t*>(&ll);
}
__device__ __forceinline__ void mma16(float d[4], const uint32_t a[4],
                                      uint32_t b0, uint32_t b1) {
    asm volatile(
        "mma.sync.aligned.m16n8k16.row.col.f32.f16.f16.f32 "
        "{%0,%1,%2,%3}, {%4,%5,%6,%7}, {%8,%9}, {%0,%1,%2,%3};"
        : "+f"(d[0]), "+f"(d[1]), "+f"(d[2]), "+f"(d[3])
        : "r"(a[0]), "r"(a[1]), "r"(a[2]), "r"(a[3]), "r"(b0), "r"(b1));
}
__device__ __forceinline__ void ldm4(uint32_t r[4], uint32_t addr) {
    asm volatile("ldmatrix.sync.aligned.m8n8.x4.shared.b16 {%0,%1,%2,%3}, [%4];"
                 : "=r"(r[0]), "=r"(r[1]), "=r"(r[2]), "=r"(r[3]) : "r"(addr));
}
__device__ __forceinline__ void cpa16(uint32_t dst, const void* src) {
    asm volatile("cp.async.cg.shared.global [%0], [%1], 16;" :: "r"(dst), "l"(src));
}
#define CP_COMMIT() asm volatile("cp.async.commit_group;" ::: "memory")
#define CP_WAIT1()  asm volatile("cp.async.wait_group 1;" ::: "memory")
#define CP_WAIT0()  asm volatile("cp.async.wait_group 0;" ::: "memory")

// smem per buffer: rows of 16 halves, row stride 48B (conflict-free ldmatrix)
//   Ah @ 0 (128x48=6144) | Al @ 6144 | Bh @ 12288 | Bl @ 18432
#define A_LO_OFF  6144
#define B_HI_OFF  12288
#define BUF_BYTES 24576
#define DYN_SMEM  (2 * BUF_BYTES)        // 49152 (default limit), 2 CTAs/SM

// ===== fp16 3x-split GEMM: cp.async packed operands, CTA 128x128, warp 32x64 ===
__global__ __launch_bounds__(256, 2)
void gemm_mma(const float* __restrict__ Af, const __half* __restrict__ Apk,
              const __half* __restrict__ Bpk0, const __half* __restrict__ Bpk1,
              const float* __restrict__ bias0, const float* __restrict__ bias1,
              const float* __restrict__ w00, const float* __restrict__ w01,
              const float* __restrict__ tg, int tIdx,
              float* __restrict__ Cf, __half* __restrict__ Cpk,
              int N, int K, int KG, int relu, int halfBlocks, int wrapA)
{
    extern __shared__ char smc[];
    const uint32_t smemBase = smem_u32(smc);

    const int tid    = threadIdx.x;
    const int lane   = tid & 31;
    const int wid    = tid >> 5;
    const int warp_m = wid & 3;        // 4 warps down M, 32 rows each
    const int warp_n = wid >> 2;       // 2 warps along N, 64 cols each
    const int mBase  = blockIdx.y * 128;
    const int nBase  = blockIdx.x * 128;
    const bool hiH   = (int)blockIdx.y >= halfBlocks;
    const __half* Bpk = hiH ? Bpk1 : Bpk0;
    const float* bias = hiH ? bias1 : bias0;
    const float* w0   = hiH ? w01   : w00;

    const int qrow = lane >> 2;
    const int qk   = lane & 3;

    float acc[2][8][4];
#pragma unroll
    for (int i = 0; i < 2; ++i)
#pragma unroll
        for (int j = 0; j < 8; ++j)
#pragma unroll
            for (int q = 0; q < 4; ++q) acc[i][j][q] = 0.f;

    // fp32-A path indices (layer-1 / volpre)
    const int rA  = tid >> 1;                  // 0..127
    const int kqA = (tid & 1) << 3;            // 0 or 8
    int arF = mBase + rA;
    if (wrapA) arF &= (BSZ - 1);

    // ldmatrix offsets
    const int l15 = lane & 15;
    const int lc  = (lane >> 4) << 4;
    const uint32_t offA0 = (uint32_t)(warp_m * 32 + l15) * 48 + lc;
    const uint32_t offA1 = offA0 + 16 * 48;
    const uint32_t offB  = (uint32_t)B_HI_OFF + (uint32_t)(warp_n * 64 + l15) * 48 + lc;

    const int nChunks = KG >> 1;

    auto issueB = [&](int kc) {
        const int kg0 = kc << 1;
        const uint32_t bb = smemBase + (kc & 1) * BUF_BYTES + B_HI_OFF;
#pragma unroll
        for (int i = 0; i < 2; ++i) {
            int u = tid + (i << 8);
            int row = u >> 2, sub = u & 3;                 // sub: kgl*2+hl
            const __half* src = Bpk +
                ((((size_t)(nBase + row)) * KG + kg0 + (sub >> 1)) * 2 + (sub & 1)) * 8;
            cpa16(bb + (sub & 1) * 6144 + row * 48 + (sub >> 1) * 16, src);
        }
    };
    auto issueApk = [&](int kc) {
        const int kg0 = kc << 1;
        const uint32_t ab = smemBase + (kc & 1) * BUF_BYTES;
#pragma unroll
        for (int i = 0; i < 2; ++i) {
            int u = tid + (i << 8);
            int row = u >> 2, sub = u & 3;
            const __half* src = Apk +
                ((((size_t)(mBase + row)) * KG + kg0 + (sub >> 1)) * 2 + (sub & 1)) * 8;
            cpa16(ab + (sub & 1) * A_LO_OFF + row * 48 + (sub >> 1) * 16, src);
        }
    };

    float4 av0, av1;
    auto prefA = [&](int kc) {
        const int gc = (kc << 4) + kqA;
        av0 = av1 = make_float4(0.f, 0.f, 0.f, 0.f);
        if (gc < K)     av0 = *(const float4*)(Af + (size_t)arF * K + gc);
        if (gc + 4 < K) av1 = *(const float4*)(Af + (size_t)arF * K + gc + 4);
    };
    auto storeA = [&](int kc) {
        char* buf = smc + (kc & 1) * BUF_BYTES;
        uint32_t h0, l0, h1, l1, h2, l2, h3, l3;
        split2(av0.x, av0.y, h0, l0); split2(av0.z, av0.w, h1, l1);
        split2(av1.x, av1.y, h2, l2); split2(av1.z, av1.w, h3, l3);
        const uint32_t ra = (uint32_t)rA * 48 + (kqA >> 3) * 16;
        *(uint4*)(buf + ra)            = make_uint4(h0, h1, h2, h3);
        *(uint4*)(buf + A_LO_OFF + ra) = make_uint4(l0, l1, l2, l3);
    };

    // prologue
    if (Af) { prefA(0); } else { issueApk(0); }
    issueB(0);
    CP_COMMIT();
    if (Af) storeA(0);

    for (int kc = 0; kc < nChunks; ++kc) {
        const bool more = (kc + 1 < nChunks);
        if (more) {
            if (Af) prefA(kc + 1); else issueApk(kc + 1);
            issueB(kc + 1);
            CP_COMMIT();
        }
        if (more) CP_WAIT1(); else CP_WAIT0();
        __syncthreads();

        const uint32_t base = smemBase + (kc & 1) * BUF_BYTES;
        uint32_t ax0[4], ax1[4], bb[4][4];
        // pass 1: Ah*Bh (bh resident)
        ldm4(ax0, base + offA0);
        ldm4(ax1, base + offA1);
#pragma unroll
        for (int t = 0; t < 4; ++t) ldm4(bb[t], base + offB + t * (16 * 48));
#pragma unroll
        for (int t = 0; t < 4; ++t) {
            mma16(acc[0][2 * t],     ax0, bb[t][0], bb[t][2]);
            mma16(acc[1][2 * t],     ax1, bb[t][0], bb[t][2]);
            mma16(acc[0][2 * t + 1], ax0, bb[t][1], bb[t][3]);
            mma16(acc[1][2 * t + 1], ax1, bb[t][1], bb[t][3]);
        }
        // pass 2: Al*Bh
        {
            uint32_t al0[4], al1[4];
            ldm4(al0, base + offA0 + A_LO_OFF);
            ldm4(al1, base + offA1 + A_LO_OFF);
#pragma unroll
            for (int t = 0; t < 4; ++t) {
                mma16(acc[0][2 * t],     al0, bb[t][0], bb[t][2]);
                mma16(acc[1][2 * t],     al1, bb[t][0], bb[t][2]);
                mma16(acc[0][2 * t + 1], al0, bb[t][1], bb[t][3]);
                mma16(acc[1][2 * t + 1], al1, bb[t][1], bb[t][3]);
            }
        }
        // pass 3: Ah*Bl (bl reuses bb regs)
#pragma unroll
        for (int t = 0; t < 4; ++t) ldm4(bb[t], base + offB + 6144 + t * (16 * 48));
#pragma unroll
        for (int t = 0; t < 4; ++t) {
            mma16(acc[0][2 * t],     ax0, bb[t][0], bb[t][2]);
            mma16(acc[1][2 * t],     ax1, bb[t][0], bb[t][2]);
            mma16(acc[0][2 * t + 1], ax0, bb[t][1], bb[t][3]);
            mma16(acc[1][2 * t + 1], ax1, bb[t][1], bb[t][3]);
        }

        if (more && Af) storeA(kc + 1);
    }

    // ---------------- epilogue ----------------
    const float tval = w0 ? __ldg(tg + tIdx) : 0.f;
    const int KGo = N >> 3;
#pragma unroll
    for (int jn = 0; jn < 8; ++jn) {
        int c = nBase + warp_n * 64 + jn * 8 + 2 * qk;
        if (c >= N) continue;
        float b0e = 0.f, b1e = 0.f;
        if (bias) { b0e = __ldg(bias + c); b1e = __ldg(bias + c + 1); }
        if (w0)   { b0e += tval * __ldg(w0 + c); b1e += tval * __ldg(w0 + c + 1); }
#pragma unroll
        for (int im = 0; im < 2; ++im) {
            int r = mBase + warp_m * 32 + im * 16 + qrow;
            float o00 = acc[im][jn][0] + b0e, o01 = acc[im][jn][1] + b1e;
            float o10 = acc[im][jn][2] + b0e, o11 = acc[im][jn][3] + b1e;
            if (relu) {
                o00 = fmaxf(o00, 0.f); o01 = fmaxf(o01, 0.f);
                o10 = fmaxf(o10, 0.f); o11 = fmaxf(o11, 0.f);
            }
            if (Cf) {
                *(float2*)(Cf + (size_t)r * N + c)       = make_float2(o00, o01);
                *(float2*)(Cf + (size_t)(r + 8) * N + c) = make_float2(o10, o11);
            } else {
                uint32_t h, l;
                const int cb = (c & 7) * 2;
                size_t u0 = ((size_t)r * KGo + (c >> 3)) * 2;
                split2(o00, o01, h, l);
                *(uint32_t*)((char*)Cpk + u0 * 16 + cb)      = h;
                *(uint32_t*)((char*)Cpk + u0 * 16 + 16 + cb) = l;
                size_t u1 = ((size_t)(r + 8) * KGo + (c >> 3)) * 2;
                split2(o10, o11, h, l);
                *(uint32_t*)((char*)Cpk + u1 * 16 + cb)      = h;
                *(uint32_t*)((char*)Cpk + u1 * 16 + 16 + cb) = l;
            }
        }
    }
}

// ---------------- one-time weight prepack (transpose + split + interleave) ----
#define S_IN  (WH * KP1)
#define S_HID (3 * WH * WH)
#define S_OUT (128 * WH)
#define S_V   (128 * KP1)
#define PP_TOTAL (2 * S_IN + 2 * S_HID + S_OUT + S_V)
__global__ void prepack_all(const float* __restrict__ Wg_in, const float* __restrict__ Wv_in,
                            const float* __restrict__ Wg_h,  const float* __restrict__ Wv_h,
                            const float* __restrict__ Wg_out, const float* __restrict__ Vm)
{
    auto wr = [](__half* dst, int row, int KGw, int k, float v) {
        __half h = __float2half_rn(v);
        __half l = __float2half_rn(v - __half2float(h));
        size_t u = ((size_t)row * KGw + (k >> 3)) * 2;
        dst[u * 8 + (k & 7)]       = h;
        dst[(u + 1) * 8 + (k & 7)] = l;
    };
    for (int i = blockIdx.x * blockDim.x + threadIdx.x; i < PP_TOTAL;
         i += gridDim.x * blockDim.x) {
        int j = i;
        if (j < S_IN) {                         // Wg_in -> [256][112]
            int n = j / KP1, k = j % KP1;
            float v = (k < DIMN) ? Wg_in[(size_t)(k + 1) * WH + n] : 0.f;
            wr(g_Win_pk[0], n, KP1 / 8, k, v);
        } else if ((j -= S_IN) < S_IN) {        // Wv_in
            int n = j / KP1, k = j % KP1;
            float v = (k < DIMN) ? Wv_in[(size_t)(k + 1) * WH + n] : 0.f;
            wr(g_Win_pk[1], n, KP1 / 8, k, v);
        } else if ((j -= S_IN) < S_HID) {       // Wg_h, row = layer*256+n
            int l = j / 65536, r = j % 65536;
            int n = r / WH, k = r % WH;
            wr(g_Wh_pk[0], l * WH + n, WH / 8, k, Wg_h[(size_t)l * 65536 + (size_t)k * WH + n]);
        } else if ((j -= S_HID) < S_HID) {      // Wv_h
            int l = j / 65536, r = j % 65536;
            int n = r / WH, k = r % WH;
            wr(g_Wh_pk[1], l * WH + n, WH / 8, k, Wv_h[(size_t)l * 65536 + (size_t)k * WH + n]);
        } else if ((j -= S_HID) < S_OUT) {      // Wg_out -> [128 pad][256]
            int n = j / WH, k = j % WH;
            float v = (n < DIMN) ? Wg_out[(size_t)k * DIMN + n] : 0.f;
            wr(g_Wout_pk, n, WH / 8, k, v);
        } else {                                // V -> [128 pad][112]
            j -= S_OUT;
            int n = j / KP1, k = j % KP1;
            float v = (n < DIMN && k < DIMN) ? Vm[(size_t)n * DIMN + k] : 0.f;
            wr(g_V_pk, n, KP1 / 8, k, v);
        }
    }
}

// ---------------- fused GEMV (packed hi/lo input) + error ----------
__global__ __launch_bounds__(256) void gemv_err(
    const __half* __restrict__ Hpk, const float* __restrict__ w,
    const float* __restrict__ b,
    const float* __restrict__ vOld, const float* __restrict__ stoch,
    const float* __restrict__ tg, int i,
    float* __restrict__ vNew, float* __restrict__ err, int doErr)
{
    __shared__ __align__(16) float ws[WH];
    ws[threadIdx.x] = w[threadIdx.x];
    __syncthreads();
    int warp = threadIdx.x >> 5, lane = threadIdx.x & 31;
    int row = blockIdx.x * 8 + warp;
    const __half* basep = Hpk + ((size_t)row * 32 + lane) * 16;
    uint4 hv = *(const uint4*)basep;
    uint4 lv = *(const uint4*)(basep + 8);
    const __half2* h2 = (const __half2*)&hv;
    const __half2* l2 = (const __half2*)&lv;
    float acc = 0.f;
#pragma unroll
    for (int q = 0; q < 4; ++q) {
        float2 hf = __half22float2(h2[q]);
        float2 lf = __half22float2(l2[q]);
        acc += (hf.x + lf.x) * ws[lane * 8 + q * 2]
             + (hf.y + lf.y) * ws[lane * 8 + q * 2 + 1];
    }
#pragma unroll
    for (int o = 16; o; o >>= 1) acc += __shfl_xor_sync(0xffffffffu, acc, o);
    if (lane == 0) {
        float v = acc + b[0];
        vNew[row] = v;
        if (doErr) {
            float h = tg[i + 1] - tg[i];
            float e = v - vOld[row] * (1.f + RRATE * h) - stoch[row];
            err[row] += e * e;
        }
    }
}

// ---------------- step: vol, stoch_int, S update ----------------
__global__ __launch_bounds__(256) void step_kernel(
    const float* __restrict__ S_old, const float* __restrict__ vp,
    const float* __restrict__ grad, const float* __restrict__ tg, int i,
    float* __restrict__ S_new, float* __restrict__ stoch)
{
    int warp = threadIdx.x >> 5, lane = threadIdx.x & 31;
    int b = blockIdx.x * 8 + warp;
    float h  = tg[i + 1] - tg[i];
    float sq = sqrtf(h);
    float rh = RRATE * h;
    const float* Sr = S_old + (size_t)b * DIMN;
    const float* vr = vp   + (size_t)b * DIMN;
    const float* gr = grad + (size_t)b * DIMN;
    float acc = 0.f;
    for (int d = lane; d < DIMN; d += 32) {
        float s   = Sr[d];
        float vol = s * (vr[d] * sq);
        acc += gr[d] * vol;
        S_new[(size_t)b * DIMN + d] = s + rh * s + vol;
    }
#pragma unroll
    for (int o = 16; o; o >>= 1) acc += __shfl_xor_sync(0xffffffffu, acc, o);
    if (lane == 0) stoch[b] = acc;
}

// ---------------- output packing: [v_f | S_f | error] ----------------
__global__ void pack_kernel(const float* __restrict__ v, const float* __restrict__ S,
                            const float* __restrict__ err, float* __restrict__ out)
{
    int i = blockIdx.x * 256 + threadIdx.x;
    if (i < BSZ * DIMN) out[BSZ + i] = S[i];
    if (i < BSZ) {
        out[i] = v[i];
        out[BSZ + BSZ * DIMN + i] = err[i];
    }
}

extern "C" void kernel_launch(void* const* d_in, const int* in_sizes, int n_in,
                              void* d_out, int out_size)
{
    const float* S0     = (const float*)d_in[0];
    const float* dW     = (const float*)d_in[1];
    const float* tg     = (const float*)d_in[2];
    const float* Vm     = (const float*)d_in[3];
    const float* Wg_in  = (const float*)d_in[4];
    const float* bg_in  = (const float*)d_in[5];
    const float* Wg_h   = (const float*)d_in[6];
    const float* bg_h   = (const float*)d_in[7];
    const float* Wg_out = (const float*)d_in[8];
    const float* bg_out = (const float*)d_in[9];
    const float* Wv_in  = (const float*)d_in[10];
    const float* bv_in  = (const float*)d_in[11];
    const float* Wv_h   = (const float*)d_in[12];
    const float* bv_h   = (const float*)d_in[13];
    const float* Wv_out = (const float*)d_in[14];
    const float* bv_out = (const float*)d_in[15];

    float *volpre, *Sb, *grad, *vb, *stoch, *err;
    __half *actA, *actB, *Win0, *Win1, *Wh0, *Wh1, *Woutp, *Vp;
    cudaGetSymbolAddress((void**)&volpre, g_volpre);
    cudaGetSymbolAddress((void**)&Sb,     g_Sbuf);
    cudaGetSymbolAddress((void**)&grad,   g_grad);
    cudaGetSymbolAddress((void**)&vb,     g_vbuf);
    cudaGetSymbolAddress((void**)&stoch,  g_stoch);
    cudaGetSymbolAddress((void**)&err,    g_err);
    cudaGetSymbolAddress((void**)&actA,   g_actA);
    cudaGetSymbolAddress((void**)&actB,   g_actB);
    cudaGetSymbolAddress((void**)&Win0,   g_Win_pk);
    Win1 = Win0 + (size_t)WH * KP1 * 2;
    cudaGetSymbolAddress((void**)&Wh0,    g_Wh_pk);
    Wh1 = Wh0 + (size_t)3 * WH * WH * 2;
    cudaGetSymbolAddress((void**)&Woutp,  g_Wout_pk);
    cudaGetSymbolAddress((void**)&Vp,     g_V_pk);

    float* Sbuf0 = Sb;
    float* Sbuf1 = Sb + (size_t)BSZ * DIMN;
    float* vA = vb;
    float* vBp = vb + BSZ;
    const size_t LOFF = (size_t)WH * WH * 2;     // per-layer halves offset (131072)
    __half* hBv = actB + (size_t)BSZ * WH * 2;   // v-half rows of actB

    // launch 0: prepack
    prepack_all<<<512, 256>>>(Wg_in, Wv_in, Wg_h, Wv_h, Wg_out, Vm);

    // launch 1: volpre = dW @ V^T (fp32 A, packed V, fp32 out)
    {
        dim3 grid(1, (NSTEP * BSZ) / 128);
        gemm_mma<<<grid, 256, DYN_SMEM>>>(dW, nullptr, Vp, Vp,
            nullptr, nullptr, nullptr, nullptr, nullptr, 0,
            volpre, nullptr, DIMN, DIMN, KP1 / 8, 0, 1 << 30, 0);
    }

    auto dual_trunk = [&](const float* S, int tIdx) {
        dim3 grid(2, 128);
        gemm_mma<<<grid, 256, DYN_SMEM>>>(S, nullptr, Win0, Win1,
            bg_in, bv_in, Wg_in, Wv_in, tg, tIdx,
            nullptr, actA, WH, DIMN, KP1 / 8, 1, 64, 1);
        gemm_mma<<<grid, 256, DYN_SMEM>>>(nullptr, actA, Wh0, Wh1,
            bg_h, bv_h, nullptr, nullptr, nullptr, 0,
            nullptr, actB, WH, WH, WH / 8, 1, 64, 0);
        gemm_mma<<<grid, 256, DYN_SMEM>>>(nullptr, actB, Wh0 + LOFF, Wh1 + LOFF,
            bg_h + WH, bv_h + WH, nullptr, nullptr, nullptr, 0,
            nullptr, actA, WH, WH, WH / 8, 1, 64, 0);
        gemm_mma<<<grid, 256, DYN_SMEM>>>(nullptr, actA, Wh0 + 2 * LOFF, Wh1 + 2 * LOFF,
            bg_h + 2 * WH, bv_h + 2 * WH, nullptr, nullptr, nullptr, 0,
            nullptr, actB, WH, WH, WH / 8, 1, 64, 0);
    };
    auto grad_gemm = [&]() {
        dim3 grid(1, 64);
        gemm_mma<<<grid, 256, DYN_SMEM>>>(nullptr, actB, Woutp, Woutp,
            bg_out, bg_out, nullptr, nullptr, nullptr, 0,
            grad, nullptr, DIMN, WH, WH / 8, 0, 1 << 30, 0);
    };

    // launches 2-5: dual trunk on [t0, S0] (ncu -s 5 lands on hidden GEMM)
    dual_trunk(S0, 0);
    grad_gemm();                                                   // grad_0
    gemv_err<<<BSZ / 8, 256>>>(hBv, Wv_out, bv_out,
                               nullptr, nullptr, tg, 0, vA, err, 0); // v_0

    cudaMemsetAsync(err, 0, BSZ * sizeof(float));

    const float* Scur = S0;
    float* vOld = vA;
    float* vNew = vBp;
    int sflip = 0;
    for (int i = 0; i < NSTEP; ++i) {
        float* Snew = sflip ? Sbuf1 : Sbuf0;
        step_kernel<<<BSZ / 8, 256>>>(Scur, volpre + (size_t)i * BSZ * DIMN,
                                      grad, tg, i, Snew, stoch);
        dual_trunk(Snew, i + 1);
        grad_gemm();                                               // grad_{i+1}
        gemv_err<<<BSZ / 8, 256>>>(hBv, Wv_out, bv_out,
                                   vOld, stoch, tg, i, vNew, err, 1); // v_{i+1}+err
        Scur = Snew; sflip ^= 1;
        float* t = vOld; vOld = vNew; vNew = t;
    }

    // output: [v_f (8192) | S_f (8192*100) | error (8192)]
    pack_kernel<<<(BSZ * DIMN) / 256, 256>>>(vOld, Scur, err, (float*)d_out);
}

// round 11
// speedup vs baseline: 1.2051x; 1.2051x over previous
#include <cuda_runtime.h>
#include <cuda_fp16.h>
#include <cstdint>
#include <cstddef>

#define BSZ   8192
#define DIMN  100
#define NSTEP 49
#define WH    256
#define RRATE 0.05f
#define KP1   112

// ---------------- device scratch (static, no allocations) ----------------
__device__ float g_volpre[(size_t)NSTEP * BSZ * DIMN];
__device__ float g_Sbuf[2][BSZ * DIMN];
__device__ float g_C[(size_t)2 * BSZ * DIMN];          // gradv out: grad rows + v rows
__device__ float g_vsave[BSZ];
__device__ float g_stoch[BSZ];
__device__ float g_err[BSZ];
__device__ float g_bvout[DIMN];
// packed activations: interleaved hi/lo 8-half groups, row stride = KG*16 halves
__device__ __align__(16) __half g_actA[(size_t)2 * BSZ * WH * 2];
__device__ __align__(16) __half g_actB[(size_t)2 * BSZ * WH * 2];
// packed weights ([n][k] K-major, split, interleaved)
__device__ __align__(16) __half g_Win_pk[2][WH * KP1 * 2];
__device__ __align__(16) __half g_Wh_pk[2][3 * WH * WH * 2];
__device__ __align__(16) __half g_Wout_pk[DIMN * WH * 2];
__device__ __align__(16) __half g_Wvout_pk[DIMN * WH * 2];
__device__ __align__(16) __half g_V_pk[DIMN * KP1 * 2];

// ---------------- helpers ----------------
__device__ __forceinline__ uint32_t smem_u32(const void* p) {
    uint32_t a;
    asm("{ .reg .u64 t; cvta.to.shared.u64 t, %1; cvt.u32.u64 %0, t; }" : "=r"(a) : "l"(p));
    return a;
}
__device__ __forceinline__ void split2(float x0, float x1, uint32_t& h, uint32_t& l) {
    __half2 hh = __floats2half2_rn(x0, x1);
    float2 hf = __half22float2(hh);
    __half2 ll = __floats2half2_rn(x0 - hf.x, x1 - hf.y);
    h = *reinterpret_cast<uint32_t*>(&hh);
    l = *reinterpret_cast<uint32_t*>(&ll);
}
__device__ __forceinline__ void mma16(float d[4], const uint32_t a[4],
                                      uint32_t b0, uint32_t b1) {
    asm volatile(
        "mma.sync.aligned.m16n8k16.row.col.f32.f16.f16.f32 "
        "{%0,%1,%2,%3}, {%4,%5,%6,%7}, {%8,%9}, {%0,%1,%2,%3};"
        : "+f"(d[0]), "+f"(d[1]), "+f"(d[2]), "+f"(d[3])
        : "r"(a[0]), "r"(a[1]), "r"(a[2]), "r"(a[3]), "r"(b0), "r"(b1));
}
__device__ __forceinline__ void ldm4(uint32_t r[4], uint32_t addr) {
    asm volatile("ldmatrix.sync.aligned.m8n8.x4.shared.b16 {%0,%1,%2,%3}, [%4];"
                 : "=r"(r[0]), "=r"(r[1]), "=r"(r[2]), "=r"(r[3]) : "r"(addr));
}

// smem per buffer: rows of 16 halves, stride 48B: Ah|Al|Bh|Bl @ 0/6144/12288/18432
#define A_LO_OFF  6144
#define B_HI_OFF  12288
#define BUF_BYTES 24576
#define DYN_SMEM  (2 * BUF_BYTES)        // 49152, 2 CTAs/SM

// ===== fp16 3x-split GEMM: LDG-staged packed/fp32 operands, CTA 128x128 =======
__global__ __launch_bounds__(256, 2)
void gemm_mma(const float* __restrict__ Af, const __half* __restrict__ Apk,
              const __half* __restrict__ Bpk0, const __half* __restrict__ Bpk1,
              const float* __restrict__ bias0, const float* __restrict__ bias1,
              const float* __restrict__ w00, const float* __restrict__ w01,
              const float* __restrict__ tg, int tIdx,
              float* __restrict__ Cf, __half* __restrict__ Cpk,
              int N, int K, int KG, int relu, int halfBlocks, int wrapA)
{
    extern __shared__ char smc[];
    const uint32_t smemBase = smem_u32(smc);

    const int tid    = threadIdx.x;
    const int lane   = tid & 31;
    const int wid    = tid >> 5;
    const int warp_m = wid & 3;        // 4 warps down M, 32 rows each
    const int warp_n = wid >> 2;       // 2 warps along N, 64 cols each
    const int mBase  = blockIdx.y * 128;
    const int nBase  = blockIdx.x * 128;
    const bool hiH   = (int)blockIdx.y >= halfBlocks;
    const __half* Bpk = hiH ? Bpk1 : Bpk0;
    const float* bias = hiH ? bias1 : bias0;
    const float* w0   = hiH ? w01   : w00;

    const int qrow = lane >> 2;
    const int qk   = lane & 3;

    float acc[2][8][4];
#pragma unroll
    for (int i = 0; i < 2; ++i)
#pragma unroll
        for (int j = 0; j < 8; ++j)
#pragma unroll
            for (int q = 0; q < 4; ++q) acc[i][j][q] = 0.f;

    // load indices: 2 threads per row, s = kgroup parity
    const int rL = tid >> 1;                   // 0..127
    const int s  = tid & 1;                    // 0/1
    int arL = mBase + rL;
    if (wrapA) arL &= (BSZ - 1);
    const int gnL = nBase + rL;
    const int kqA = s << 3;                    // fp32-A: k offset 0/8

    // ldmatrix offsets
    const int l15 = lane & 15;
    const int lc  = (lane >> 4) << 4;
    const uint32_t offA0 = (uint32_t)(warp_m * 32 + l15) * 48 + lc;
    const uint32_t offA1 = offA0 + 16 * 48;
    const uint32_t offB  = (uint32_t)B_HI_OFF + (uint32_t)(warp_n * 64 + l15) * 48 + lc;

    const int nChunks = KG >> 1;

    float4 av0, av1;
    uint4 pa0, pa1, pb0, pb1;
    auto prefetch = [&](int kc) {
        if (Af) {
            const int gc = (kc << 4) + kqA;
            av0 = av1 = make_float4(0.f, 0.f, 0.f, 0.f);
            if (gc < K)     av0 = *(const float4*)(Af + (size_t)arL * K + gc);
            if (gc + 4 < K) av1 = *(const float4*)(Af + (size_t)arL * K + gc + 4);
        } else {
            const size_t ua = ((size_t)arL * KG + (kc << 1) + s) * 16;
            pa0 = *(const uint4*)(Apk + ua);
            pa1 = *(const uint4*)(Apk + ua + 8);
        }
        if (gnL < N) {
            const size_t ub = ((size_t)gnL * KG + (kc << 1) + s) * 16;
            pb0 = *(const uint4*)(Bpk + ub);
            pb1 = *(const uint4*)(Bpk + ub + 8);
        } else {
            pb0 = pb1 = make_uint4(0, 0, 0, 0);
        }
    };
    auto store = [&](int b) {
        char* buf = smc + b * BUF_BYTES;
        const uint32_t ro = (uint32_t)rL * 48 + s * 16;
        if (Af) {
            uint32_t h0, l0, h1, l1, h2, l2, h3, l3;
            split2(av0.x, av0.y, h0, l0); split2(av0.z, av0.w, h1, l1);
            split2(av1.x, av1.y, h2, l2); split2(av1.z, av1.w, h3, l3);
            *(uint4*)(buf + ro)            = make_uint4(h0, h1, h2, h3);
            *(uint4*)(buf + A_LO_OFF + ro) = make_uint4(l0, l1, l2, l3);
        } else {
            *(uint4*)(buf + ro)            = pa0;
            *(uint4*)(buf + A_LO_OFF + ro) = pa1;
        }
        *(uint4*)(buf + B_HI_OFF + ro)        = pb0;
        *(uint4*)(buf + B_HI_OFF + 6144 + ro) = pb1;
    };

    prefetch(0);
    store(0);

    for (int kc = 0; kc < nChunks; ++kc) {
        __syncthreads();
        const bool more = (kc + 1 < nChunks);
        if (more) prefetch(kc + 1);

        const uint32_t base = smemBase + (kc & 1) * BUF_BYTES;
        uint32_t ax0[4], ax1[4], bb[4][4];
        // pass 1: Ah*Bh (bh resident)
        ldm4(ax0, base + offA0);
        ldm4(ax1, base + offA1);
#pragma unroll
        for (int t = 0; t < 4; ++t) ldm4(bb[t], base + offB + t * (16 * 48));
#pragma unroll
        for (int t = 0; t < 4; ++t) {
            mma16(acc[0][2 * t],     ax0, bb[t][0], bb[t][2]);
            mma16(acc[1][2 * t],     ax1, bb[t][0], bb[t][2]);
            mma16(acc[0][2 * t + 1], ax0, bb[t][1], bb[t][3]);
            mma16(acc[1][2 * t + 1], ax1, bb[t][1], bb[t][3]);
        }
        // pass 2: Al*Bh
        {
            uint32_t al0[4], al1[4];
            ldm4(al0, base + offA0 + A_LO_OFF);
            ldm4(al1, base + offA1 + A_LO_OFF);
#pragma unroll
            for (int t = 0; t < 4; ++t) {
                mma16(acc[0][2 * t],     al0, bb[t][0], bb[t][2]);
                mma16(acc[1][2 * t],     al1, bb[t][0], bb[t][2]);
                mma16(acc[0][2 * t + 1], al0, bb[t][1], bb[t][3]);
                mma16(acc[1][2 * t + 1], al1, bb[t][1], bb[t][3]);
            }
        }
        // pass 3: Ah*Bl (bl reuses bb regs)
#pragma unroll
        for (int t = 0; t < 4; ++t) ldm4(bb[t], base + offB + 6144 + t * (16 * 48));
#pragma unroll
        for (int t = 0; t < 4; ++t) {
            mma16(acc[0][2 * t],     ax0, bb[t][0], bb[t][2]);
            mma16(acc[1][2 * t],     ax1, bb[t][0], bb[t][2]);
            mma16(acc[0][2 * t + 1], ax0, bb[t][1], bb[t][3]);
            mma16(acc[1][2 * t + 1], ax1, bb[t][1], bb[t][3]);
        }

        if (more) store((kc + 1) & 1);
    }

    // ---------------- epilogue ----------------
    const float tval = w0 ? __ldg(tg + tIdx) : 0.f;
    const int KGo = N >> 3;
#pragma unroll
    for (int jn = 0; jn < 8; ++jn) {
        int c = nBase + warp_n * 64 + jn * 8 + 2 * qk;
        if (c >= N) continue;
        float b0e = 0.f, b1e = 0.f;
        if (bias) { b0e = __ldg(bias + c); b1e = __ldg(bias + c + 1); }
        if (w0)   { b0e += tval * __ldg(w0 + c); b1e += tval * __ldg(w0 + c + 1); }
#pragma unroll
        for (int im = 0; im < 2; ++im) {
            int r = mBase + warp_m * 32 + im * 16 + qrow;
            float o00 = acc[im][jn][0] + b0e, o01 = acc[im][jn][1] + b1e;
            float o10 = acc[im][jn][2] + b0e, o11 = acc[im][jn][3] + b1e;
            if (relu) {
                o00 = fmaxf(o00, 0.f); o01 = fmaxf(o01, 0.f);
                o10 = fmaxf(o10, 0.f); o11 = fmaxf(o11, 0.f);
            }
            if (Cf) {
                *(float2*)(Cf + (size_t)r * N + c)       = make_float2(o00, o01);
                *(float2*)(Cf + (size_t)(r + 8) * N + c) = make_float2(o10, o11);
            } else {
                uint32_t h, l;
                const int cb = (c & 7) * 2;
                size_t u0 = ((size_t)r * KGo + (c >> 3)) * 2;
                split2(o00, o01, h, l);
                *(uint32_t*)((char*)Cpk + u0 * 16 + cb)      = h;
                *(uint32_t*)((char*)Cpk + u0 * 16 + 16 + cb) = l;
                size_t u1 = ((size_t)(r + 8) * KGo + (c >> 3)) * 2;
                split2(o10, o11, h, l);
                *(uint32_t*)((char*)Cpk + u1 * 16 + cb)      = h;
                *(uint32_t*)((char*)Cpk + u1 * 16 + 16 + cb) = l;
            }
        }
    }
}

// ---------------- one-time weight prepack ----------------
#define S_IN   (WH * KP1)
#define S_HID  (3 * WH * WH)
#define S_OUT  (DIMN * WH)
#define S_V    (DIMN * KP1)
#define PP_TOTAL (2 * S_IN + 2 * S_HID + 2 * S_OUT + S_V + DIMN)
__global__ void prepack_all(const float* __restrict__ Wg_in, const float* __restrict__ Wv_in,
                            const float* __restrict__ Wg_h,  const float* __restrict__ Wv_h,
                            const float* __restrict__ Wg_out, const float* __restrict__ Wv_out,
                            const float* __restrict__ bv_out, const float* __restrict__ Vm)
{
    auto wr = [](__half* dst, int row, int KGw, int k, float v) {
        __half h = __float2half_rn(v);
        __half l = __float2half_rn(v - __half2float(h));
        size_t u = ((size_t)row * KGw + (k >> 3)) * 2;
        dst[u * 8 + (k & 7)]       = h;
        dst[(u + 1) * 8 + (k & 7)] = l;
    };
    for (int i = blockIdx.x * blockDim.x + threadIdx.x; i < PP_TOTAL;
         i += gridDim.x * blockDim.x) {
        int j = i;
        if (j < S_IN) {
            int n = j / KP1, k = j % KP1;
            wr(g_Win_pk[0], n, KP1 / 8, k, (k < DIMN) ? Wg_in[(size_t)(k + 1) * WH + n] : 0.f);
        } else if ((j -= S_IN) < S_IN) {
            int n = j / KP1, k = j % KP1;
            wr(g_Win_pk[1], n, KP1 / 8, k, (k < DIMN) ? Wv_in[(size_t)(k + 1) * WH + n] : 0.f);
        } else if ((j -= S_IN) < S_HID) {
            int l = j / 65536, r = j % 65536;
            int n = r / WH, k = r % WH;
            wr(g_Wh_pk[0], l * WH + n, WH / 8, k, Wg_h[(size_t)l * 65536 + (size_t)k * WH + n]);
        } else if ((j -= S_HID) < S_HID) {
            int l = j / 65536, r = j % 65536;
            int n = r / WH, k = r % WH;
            wr(g_Wh_pk[1], l * WH + n, WH / 8, k, Wv_h[(size_t)l * 65536 + (size_t)k * WH + n]);
        } else if ((j -= S_HID) < S_OUT) {               // grad output weights
            int n = j / WH, k = j % WH;
            wr(g_Wout_pk, n, WH / 8, k, Wg_out[(size_t)k * DIMN + n]);
        } else if ((j -= S_OUT) < S_OUT) {               // v output weights (col 0 only)
            int n = j / WH, k = j % WH;
            wr(g_Wvout_pk, n, WH / 8, k, (n == 0) ? Wv_out[k] : 0.f);
        } else if ((j -= S_OUT) < S_V) {                 // volatility matrix
            int n = j / KP1, k = j % KP1;
            wr(g_V_pk, n, KP1 / 8, k, (k < DIMN) ? Vm[(size_t)n * DIMN + k] : 0.f);
        } else {                                         // bvout vector
            j -= S_V;
            g_bvout[j] = (j == 0) ? bv_out[0] : 0.f;
        }
    }
}

// ---------------- step (+ previous-step error) ----------------
__global__ __launch_bounds__(256) void step_err(
    const float* __restrict__ S_old, const float* __restrict__ vp,
    const float* __restrict__ grad, const float* __restrict__ Cv,
    const float* __restrict__ tg, int i,
    float* __restrict__ S_new, float* __restrict__ stoch,
    float* __restrict__ vsave, float* __restrict__ err)
{
    int warp = threadIdx.x >> 5, lane = threadIdx.x & 31;
    int b = blockIdx.x * 8 + warp;
    float h  = tg[i + 1] - tg[i];
    float sq = sqrtf(h);
    float rh = RRATE * h;
    // previous step's error term (uses old stoch/vsave before overwrite)
    if (lane == 0) {
        float vC = Cv[(size_t)b * DIMN];
        if (i > 0) {
            float hp = tg[i] - tg[i - 1];
            float e = vC - vsave[b] * (1.f + RRATE * hp) - stoch[b];
            err[b] += e * e;
        }
        vsave[b] = vC;
    }
    const float* Sr = S_old + (size_t)b * DIMN;
    const float* vr = vp   + (size_t)b * DIMN;
    const float* gr = grad + (size_t)b * DIMN;
    float acc = 0.f;
    for (int d = lane; d < DIMN; d += 32) {
        float s   = Sr[d];
        float vol = s * (vr[d] * sq);
        acc += gr[d] * vol;
        S_new[(size_t)b * DIMN + d] = s + rh * s + vol;
    }
#pragma unroll
    for (int o = 16; o; o >>= 1) acc += __shfl_xor_sync(0xffffffffu, acc, o);
    if (lane == 0) stoch[b] = acc;
}

// ---------------- output packing + final error term ----------------
__global__ void pack_kernel(const float* __restrict__ Cv, const float* __restrict__ S,
                            const float* __restrict__ vsave, const float* __restrict__ stoch,
                            const float* __restrict__ tg, float* __restrict__ err,
                            float* __restrict__ out)
{
    int i = blockIdx.x * 256 + threadIdx.x;
    if (i < BSZ * DIMN) out[BSZ + i] = S[i];
    if (i < BSZ) {
        float vC = Cv[(size_t)i * DIMN];
        float hp = tg[NSTEP] - tg[NSTEP - 1];
        float e = vC - vsave[i] * (1.f + RRATE * hp) - stoch[i];
        out[i] = vC;
        out[BSZ + BSZ * DIMN + i] = err[i] + e * e;
    }
}

extern "C" void kernel_launch(void* const* d_in, const int* in_sizes, int n_in,
                              void* d_out, int out_size)
{
    const float* S0     = (const float*)d_in[0];
    const float* dW     = (const float*)d_in[1];
    const float* tg     = (const float*)d_in[2];
    const float* Vm     = (const float*)d_in[3];
    const float* Wg_in  = (const float*)d_in[4];
    const float* bg_in  = (const float*)d_in[5];
    const float* Wg_h   = (const float*)d_in[6];
    const float* bg_h   = (const float*)d_in[7];
    const float* Wg_out = (const float*)d_in[8];
    const float* bg_out = (const float*)d_in[9];
    const float* Wv_in  = (const float*)d_in[10];
    const float* bv_in  = (const float*)d_in[11];
    const float* Wv_h   = (const float*)d_in[12];
    const float* bv_h   = (const float*)d_in[13];
    const float* Wv_out = (const float*)d_in[14];
    const float* bv_out = (const float*)d_in[15];

    float *volpre, *Sb, *Cbuf, *vsave, *stoch, *err, *bvout;
    __half *actA, *actB, *Win0, *Win1, *Wh0, *Wh1, *Woutp, *Wvoutp, *Vp;
    cudaGetSymbolAddress((void**)&volpre, g_volpre);
    cudaGetSymbolAddress((void**)&Sb,     g_Sbuf);
    cudaGetSymbolAddress((void**)&Cbuf,   g_C);
    cudaGetSymbolAddress((void**)&vsave,  g_vsave);
    cudaGetSymbolAddress((void**)&stoch,  g_stoch);
    cudaGetSymbolAddress((void**)&err,    g_err);
    cudaGetSymbolAddress((void**)&bvout,  g_bvout);
    cudaGetSymbolAddress((void**)&actA,   g_actA);
    cudaGetSymbolAddress((void**)&actB,   g_actB);
    cudaGetSymbolAddress((void**)&Win0,   g_Win_pk);
    Win1 = Win0 + (size_t)WH * KP1 * 2;
    cudaGetSymbolAddress((void**)&Wh0,    g_Wh_pk);
    Wh1 = Wh0 + (size_t)3 * WH * WH * 2;
    cudaGetSymbolAddress((void**)&Woutp,  g_Wout_pk);
    cudaGetSymbolAddress((void**)&Wvoutp, g_Wvout_pk);
    cudaGetSymbolAddress((void**)&Vp,     g_V_pk);

    float* Sbuf0 = Sb;
    float* Sbuf1 = Sb + (size_t)BSZ * DIMN;
    float* Cv = Cbuf + (size_t)BSZ * DIMN;      // v-half of gradv output
    const size_t LOFF = (size_t)WH * WH * 2;

    // launch 0: prepack
    prepack_all<<<512, 256>>>(Wg_in, Wv_in, Wg_h, Wv_h, Wg_out, Wv_out, bv_out, Vm);

    // launch 1: volpre = dW @ V^T
    {
        dim3 grid(1, (NSTEP * BSZ) / 128);
        gemm_mma<<<grid, 256, DYN_SMEM>>>(dW, nullptr, Vp, Vp,
            nullptr, nullptr, nullptr, nullptr, nullptr, 0,
            volpre, nullptr, DIMN, DIMN, KP1 / 8, 0, 1 << 30, 0);
    }

    auto dual_trunk = [&](const float* S, int tIdx) {
        dim3 grid(2, 128);
        gemm_mma<<<grid, 256, DYN_SMEM>>>(S, nullptr, Win0, Win1,
            bg_in, bv_in, Wg_in, Wv_in, tg, tIdx,
            nullptr, actA, WH, DIMN, KP1 / 8, 1, 64, 1);
        gemm_mma<<<grid, 256, DYN_SMEM>>>(nullptr, actA, Wh0, Wh1,
            bg_h, bv_h, nullptr, nullptr, nullptr, 0,
            nullptr, actB, WH, WH, WH / 8, 1, 64, 0);
        gemm_mma<<<grid, 256, DYN_SMEM>>>(nullptr, actB, Wh0 + LOFF, Wh1 + LOFF,
            bg_h + WH, bv_h + WH, nullptr, nullptr, nullptr, 0,
            nullptr, actA, WH, WH, WH / 8, 1, 64, 0);
        gemm_mma<<<grid, 256, DYN_SMEM>>>(nullptr, actA, Wh0 + 2 * LOFF, Wh1 + 2 * LOFF,
            bg_h + 2 * WH, bv_h + 2 * WH, nullptr, nullptr, nullptr, 0,
            nullptr, actB, WH, WH, WH / 8, 1, 64, 0);
    };
    auto gradv = [&]() {   // grad (rows 0..8191) + v col 0 (rows 8192..)
        dim3 grid(1, 128);
        gemm_mma<<<grid, 256, DYN_SMEM>>>(nullptr, actB, Woutp, Wvoutp,
            bg_out, bvout, nullptr, nullptr, nullptr, 0,
            Cbuf, nullptr, DIMN, WH, WH / 8, 0, 64, 0);
    };

    // launches 2-5: dual trunk on [t0, S0] (launch 5 = hidden GEMM for ncu)
    dual_trunk(S0, 0);
    gradv();                                      // grad_0, v_0
    cudaMemsetAsync(err, 0, BSZ * sizeof(float));

    const float* Scur = S0;
    int sflip = 0;
    for (int i = 0; i < NSTEP; ++i) {
        float* Snew = sflip ? Sbuf1 : Sbuf0;
        // step i: S update + stoch_i + err_{i-1} + vsave = v_i
        step_err<<<BSZ / 8, 256>>>(Scur, volpre + (size_t)i * BSZ * DIMN,
                                   Cbuf, Cv, tg, i, Snew, stoch, vsave, err);
        dual_trunk(Snew, i + 1);
        gradv();                                  // grad_{i+1}, v_{i+1}
        Scur = Snew; sflip ^= 1;
    }

    // output: [v_f | S_f | error]  (err_48 folded in)
    pack_kernel<<<(BSZ * DIMN) / 256, 256>>>(Cv, Scur, vsave, stoch, tg, err,
                                             (float*)d_out);
}

// round 12
// speedup vs baseline: 1.3357x; 1.1084x over previous
#include <cuda_runtime.h>
#include <cuda_fp16.h>
#include <cstdint>
#include <cstddef>

#define BSZ   8192
#define DIMN  100
#define NSTEP 49
#define WH    256
#define RRATE 0.05f

// ---------------- device scratch (static, no allocations) ----------------
__device__ float g_volpre[(size_t)NSTEP * BSZ * DIMN];
__device__ float g_Sbuf[2][BSZ * DIMN];
__device__ float g_hdual[2][(size_t)2 * BSZ * WH];     // dual-MLP activations [16384][256]
__device__ float g_C[(size_t)2 * BSZ * DIMN];          // gradv out: grad rows | v rows
__device__ float g_vsave[BSZ];
__device__ float g_stoch[BSZ];
__device__ float g_err[BSZ];
__device__ float g_bvout[DIMN];
// transposed weights: Wt[n*K + k] = W[k*N + n]
__device__ float g_Wgt_in[WH * DIMN];
__device__ float g_Wgt_h[3][WH * WH];
__device__ float g_Wgt_out[DIMN * WH];
__device__ float g_Wvt_out[DIMN * WH];
__device__ float g_Wvt_in[WH * DIMN];
__device__ float g_Wvt_h[3][WH * WH];

// ---------------- helpers ----------------
__device__ __forceinline__ uint32_t smem_u32(const void* p) {
    uint32_t a;
    asm("{ .reg .u64 t; cvta.to.shared.u64 t, %1; cvt.u32.u64 %0, t; }" : "=r"(a) : "l"(p));
    return a;
}
__device__ __forceinline__ void split2(float x0, float x1, uint32_t& h, uint32_t& l) {
    __half2 hh = __floats2half2_rn(x0, x1);
    float2 hf = __half22float2(hh);
    __half2 ll = __floats2half2_rn(x0 - hf.x, x1 - hf.y);
    h = *reinterpret_cast<uint32_t*>(&hh);
    l = *reinterpret_cast<uint32_t*>(&ll);
}
__device__ __forceinline__ void mma16(float d[4], const uint32_t a[4],
                                      uint32_t b0, uint32_t b1) {
    asm volatile(
        "mma.sync.aligned.m16n8k16.row.col.f32.f16.f16.f32 "
        "{%0,%1,%2,%3}, {%4,%5,%6,%7}, {%8,%9}, {%0,%1,%2,%3};"
        : "+f"(d[0]), "+f"(d[1]), "+f"(d[2]), "+f"(d[3])
        : "r"(a[0]), "r"(a[1]), "r"(a[2]), "r"(a[3]), "r"(b0), "r"(b1));
}
__device__ __forceinline__ void ldm4(uint32_t r[4], uint32_t addr) {
    asm volatile("ldmatrix.sync.aligned.m8n8.x4.shared.b16 {%0,%1,%2,%3}, [%4];"
                 : "=r"(r[0]), "=r"(r[1]), "=r"(r[2]), "=r"(r[3]) : "r"(addr));
}

// smem per buffer: rows of 16 halves, row stride 48B (conflict-free)
#define A_LO_OFF  6144
#define B_HI_OFF  12288
#define B_LO_OFF  18432
#define BUF_BYTES 24576
#define DYN_SMEM  (2 * BUF_BYTES)        // 49152, 2 CTAs/SM

// ========== R7 GEMM: fp16 3x-split, dual-weight, CTA 128x128, warp 32x64 ======
__global__ __launch_bounds__(256, 2)
void gemm_mma(const float* __restrict__ A,
              const float* __restrict__ Wt0, const float* __restrict__ Wt1,
              const float* __restrict__ bias0, const float* __restrict__ bias1,
              const float* __restrict__ w00, const float* __restrict__ w01,
              const float* __restrict__ tg, int tIdx,
              float* __restrict__ C, int N, int K, int relu,
              int halfBlocks, int wrapA)
{
    extern __shared__ uint32_t smw[];
    char* smc = (char*)smw;
    const uint32_t smemBase = smem_u32(smw);

    const int tid    = threadIdx.x;
    const int lane   = tid & 31;
    const int wid    = tid >> 5;
    const int warp_m = wid & 3;
    const int warp_n = wid >> 2;
    const int mBase  = blockIdx.y * 128;
    const int nBase  = blockIdx.x * 128;
    const bool hiH   = (int)blockIdx.y >= halfBlocks;
    const float* Wt   = hiH ? Wt1   : Wt0;
    const float* bias = hiH ? bias1 : bias0;
    const float* w0   = hiH ? w01   : w00;

    const int qrow = lane >> 2;
    const int qk   = lane & 3;

    float acc[2][8][4];
#pragma unroll
    for (int i = 0; i < 2; ++i)
#pragma unroll
        for (int j = 0; j < 8; ++j)
#pragma unroll
            for (int q = 0; q < 4; ++q) acc[i][j][q] = 0.f;

    const int r0  = tid >> 2;
    const int r1  = r0 + 64;
    const int c40 = (tid & 3) << 2;
    int ar0 = mBase + r0, ar1 = mBase + r1;
    if (wrapA) { ar0 &= (BSZ - 1); ar1 &= (BSZ - 1); }
    const int gn0 = nBase + r0, gn1 = nBase + r1;

    const int l15 = lane & 15;
    const int lc  = (lane >> 4) << 4;
    const uint32_t offA0 = (uint32_t)(warp_m * 32 + l15) * 48 + lc;
    const uint32_t offA1 = offA0 + 16 * 48;
    const uint32_t offB  = (uint32_t)B_HI_OFF + (uint32_t)(warp_n * 64 + l15) * 48 + lc;

    const int nChunks = (K + 15) >> 4;

    float4 av0, av1, bv0, bv1;
    auto prefetch = [&](int kc) {
        const int gc = (kc << 4) + c40;
        av0 = av1 = bv0 = bv1 = make_float4(0.f, 0.f, 0.f, 0.f);
        if (gc < K) {
            av0 = *(const float4*)(A + (size_t)ar0 * K + gc);
            av1 = *(const float4*)(A + (size_t)ar1 * K + gc);
            if (gn0 < N) bv0 = *(const float4*)(Wt + (size_t)gn0 * K + gc);
            if (gn1 < N) bv1 = *(const float4*)(Wt + (size_t)gn1 * K + gc);
        }
    };
    auto store = [&](int b) {
        char* buf = smc + b * BUF_BYTES;
        const uint32_t rowOff0 = (uint32_t)r0 * 48 + c40 * 2;
        const uint32_t rowOff1 = (uint32_t)r1 * 48 + c40 * 2;
        uint32_t h0, l0, h1, l1;
        split2(av0.x, av0.y, h0, l0); split2(av0.z, av0.w, h1, l1);
        *(uint2*)(buf + rowOff0)            = make_uint2(h0, h1);
        *(uint2*)(buf + A_LO_OFF + rowOff0) = make_uint2(l0, l1);
        split2(av1.x, av1.y, h0, l0); split2(av1.z, av1.w, h1, l1);
        *(uint2*)(buf + rowOff1)            = make_uint2(h0, h1);
        *(uint2*)(buf + A_LO_OFF + rowOff1) = make_uint2(l0, l1);
        split2(bv0.x, bv0.y, h0, l0); split2(bv0.z, bv0.w, h1, l1);
        *(uint2*)(buf + B_HI_OFF + rowOff0) = make_uint2(h0, h1);
        *(uint2*)(buf + B_LO_OFF + rowOff0) = make_uint2(l0, l1);
        split2(bv1.x, bv1.y, h0, l0); split2(bv1.z, bv1.w, h1, l1);
        *(uint2*)(buf + B_HI_OFF + rowOff1) = make_uint2(h0, h1);
        *(uint2*)(buf + B_LO_OFF + rowOff1) = make_uint2(l0, l1);
    };

    prefetch(0);
    store(0);

    for (int kc = 0; kc < nChunks; ++kc) {
        __syncthreads();
        const bool more = (kc + 1 < nChunks);
        if (more) prefetch(kc + 1);

        const uint32_t base = smemBase + (kc & 1) * BUF_BYTES;

        uint32_t ax0[4], ax1[4], bb[4][4];
        // pass 1: Ah * Bh (bh resident)
        ldm4(ax0, base + offA0);
        ldm4(ax1, base + offA1);
#pragma unroll
        for (int t = 0; t < 4; ++t) ldm4(bb[t], base + offB + t * (16 * 48));
#pragma unroll
        for (int t = 0; t < 4; ++t) {
            mma16(acc[0][2 * t],     ax0, bb[t][0], bb[t][2]);
            mma16(acc[1][2 * t],     ax1, bb[t][0], bb[t][2]);
            mma16(acc[0][2 * t + 1], ax0, bb[t][1], bb[t][3]);
            mma16(acc[1][2 * t + 1], ax1, bb[t][1], bb[t][3]);
        }
        // pass 2: Al * Bh
        {
            uint32_t al0[4], al1[4];
            ldm4(al0, base + offA0 + A_LO_OFF);
            ldm4(al1, base + offA1 + A_LO_OFF);
#pragma unroll
            for (int t = 0; t < 4; ++t) {
                mma16(acc[0][2 * t],     al0, bb[t][0], bb[t][2]);
                mma16(acc[1][2 * t],     al1, bb[t][0], bb[t][2]);
                mma16(acc[0][2 * t + 1], al0, bb[t][1], bb[t][3]);
                mma16(acc[1][2 * t + 1], al1, bb[t][1], bb[t][3]);
            }
        }
        // pass 3: Ah * Bl
#pragma unroll
        for (int t = 0; t < 4; ++t)
            ldm4(bb[t], base + offB + (B_LO_OFF - B_HI_OFF) + t * (16 * 48));
#pragma unroll
        for (int t = 0; t < 4; ++t) {
            mma16(acc[0][2 * t],     ax0, bb[t][0], bb[t][2]);
            mma16(acc[1][2 * t],     ax1, bb[t][0], bb[t][2]);
            mma16(acc[0][2 * t + 1], ax0, bb[t][1], bb[t][3]);
            mma16(acc[1][2 * t + 1], ax1, bb[t][1], bb[t][3]);
        }

        if (more) store((kc + 1) & 1);
    }

    // ---------------- epilogue ----------------
    const float tval = w0 ? __ldg(tg + tIdx) : 0.f;
#pragma unroll
    for (int jn = 0; jn < 8; ++jn) {
        int c = nBase + warp_n * 64 + jn * 8 + 2 * qk;
        if (c >= N) continue;
        float b0e = 0.f, b1e = 0.f;
        if (bias) { b0e = __ldg(bias + c); b1e = __ldg(bias + c + 1); }
        if (w0)   { b0e += tval * __ldg(w0 + c); b1e += tval * __ldg(w0 + c + 1); }
#pragma unroll
        for (int im = 0; im < 2; ++im) {
            int r = mBase + warp_m * 32 + im * 16 + qrow;
            float o00 = acc[im][jn][0] + b0e, o01 = acc[im][jn][1] + b1e;
            float o10 = acc[im][jn][2] + b0e, o11 = acc[im][jn][3] + b1e;
            if (relu) {
                o00 = fmaxf(o00, 0.f); o01 = fmaxf(o01, 0.f);
                o10 = fmaxf(o10, 0.f); o11 = fmaxf(o11, 0.f);
            }
            *(float2*)(C + (size_t)r * N + c)       = make_float2(o00, o01);
            *(float2*)(C + (size_t)(r + 8) * N + c) = make_float2(o10, o11);
        }
    }
}

// ---------------- fused weight transposes (ONE launch) ----------------
#define WT_TOTAL (25600 * 2 + 196608 * 2 + 25600 * 2 + DIMN)
__global__ void wtrans_all(const float* __restrict__ Wg_in, const float* __restrict__ Wv_in,
                           const float* __restrict__ Wg_h,  const float* __restrict__ Wv_h,
                           const float* __restrict__ Wg_out, const float* __restrict__ Wv_out,
                           const float* __restrict__ bv_out)
{
    for (int i = blockIdx.x * blockDim.x + threadIdx.x; i < WT_TOTAL;
         i += gridDim.x * blockDim.x) {
        int j = i;
        if (j < 25600) {                       // Wg_in (101x256, skip row 0) -> [256][100]
            int n = j / 100, k = j % 100;
            g_Wgt_in[j] = Wg_in[(size_t)(k + 1) * WH + n];
        } else if ((j -= 25600) < 25600) {     // Wv_in
            int n = j / 100, k = j % 100;
            g_Wvt_in[j] = Wv_in[(size_t)(k + 1) * WH + n];
        } else if ((j -= 25600) < 196608) {    // Wg_h
            int l = j / 65536, r = j % 65536;
            int n = r / 256, k = r % 256;
            (&g_Wgt_h[0][0])[j] = Wg_h[(size_t)l * 65536 + (size_t)k * WH + n];
        } else if ((j -= 196608) < 196608) {   // Wv_h
            int l = j / 65536, r = j % 65536;
            int n = r / 256, k = r % 256;
            (&g_Wvt_h[0][0])[j] = Wv_h[(size_t)l * 65536 + (size_t)k * WH + n];
        } else if ((j -= 196608) < 25600) {    // Wg_out (256x100) -> [100][256]
            int n = j / 256, k = j % 256;
            g_Wgt_out[j] = Wg_out[(size_t)k * DIMN + n];
        } else if ((j -= 25600) < 25600) {     // Wv_out (256x1) -> row 0 of [100][256]
            int n = j / 256, k = j % 256;
            g_Wvt_out[j] = (n == 0) ? Wv_out[k] : 0.f;
        } else {                               // bvout padded bias
            j -= 25600;
            g_bvout[j] = (j == 0) ? bv_out[0] : 0.f;
        }
    }
}

// ---------------- step (+ previous-step error, vsave) ----------------
__global__ __launch_bounds__(256) void step_err(
    const float* __restrict__ S_old, const float* __restrict__ vp,
    const float* __restrict__ grad, const float* __restrict__ Cv,
    const float* __restrict__ tg, int i,
    float* __restrict__ S_new, float* __restrict__ stoch,
    float* __restrict__ vsave, float* __restrict__ err)
{
    int warp = threadIdx.x >> 5, lane = threadIdx.x & 31;
    int b = blockIdx.x * 8 + warp;
    float h  = tg[i + 1] - tg[i];
    float sq = sqrtf(h);
    float rh = RRATE * h;
    if (lane == 0) {
        float vC = Cv[(size_t)b * DIMN];
        if (i > 0) {
            float hp = tg[i] - tg[i - 1];
            float e = vC - vsave[b] * (1.f + RRATE * hp) - stoch[b];
            err[b] += e * e;
        }
        vsave[b] = vC;
    }
    const float* Sr = S_old + (size_t)b * DIMN;
    const float* vr = vp   + (size_t)b * DIMN;
    const float* gr = grad + (size_t)b * DIMN;
    float acc = 0.f;
    for (int d = lane; d < DIMN; d += 32) {
        float s   = Sr[d];
        float vol = s * (vr[d] * sq);
        acc += gr[d] * vol;
        S_new[(size_t)b * DIMN + d] = s + rh * s + vol;
    }
#pragma unroll
    for (int o = 16; o; o >>= 1) acc += __shfl_xor_sync(0xffffffffu, acc, o);
    if (lane == 0) stoch[b] = acc;
}

// ---------------- output packing + final error term ----------------
__global__ void pack_kernel(const float* __restrict__ Cv, const float* __restrict__ S,
                            const float* __restrict__ vsave, const float* __restrict__ stoch,
                            const float* __restrict__ tg, const float* __restrict__ err,
                            float* __restrict__ out)
{
    int i = blockIdx.x * 256 + threadIdx.x;
    if (i < BSZ * DIMN) out[BSZ + i] = S[i];
    if (i < BSZ) {
        float vC = Cv[(size_t)i * DIMN];
        float hp = tg[NSTEP] - tg[NSTEP - 1];
        float e = vC - vsave[i] * (1.f + RRATE * hp) - stoch[i];
        out[i] = vC;
        out[BSZ + BSZ * DIMN + i] = err[i] + e * e;
    }
}

extern "C" void kernel_launch(void* const* d_in, const int* in_sizes, int n_in,
                              void* d_out, int out_size)
{
    const float* S0     = (const float*)d_in[0];
    const float* dW     = (const float*)d_in[1];
    const float* tg     = (const float*)d_in[2];
    const float* Vm     = (const float*)d_in[3];
    const float* Wg_in  = (const float*)d_in[4];
    const float* bg_in  = (const float*)d_in[5];
    const float* Wg_h   = (const float*)d_in[6];
    const float* bg_h   = (const float*)d_in[7];
    const float* Wg_out = (const float*)d_in[8];
    const float* bg_out = (const float*)d_in[9];
    const float* Wv_in  = (const float*)d_in[10];
    const float* bv_in  = (const float*)d_in[11];
    const float* Wv_h   = (const float*)d_in[12];
    const float* bv_h   = (const float*)d_in[13];
    const float* Wv_out = (const float*)d_in[14];
    const float* bv_out = (const float*)d_in[15];

    float *volpre, *Sb, *hd, *Cbuf, *vsave, *stoch, *err, *bvout;
    float *Wgt_in, *Wgt_h, *Wgt_out, *Wvt_out, *Wvt_in, *Wvt_h;
    cudaGetSymbolAddress((void**)&volpre, g_volpre);
    cudaGetSymbolAddress((void**)&Sb,     g_Sbuf);
    cudaGetSymbolAddress((void**)&hd,     g_hdual);
    cudaGetSymbolAddress((void**)&Cbuf,   g_C);
    cudaGetSymbolAddress((void**)&vsave,  g_vsave);
    cudaGetSymbolAddress((void**)&stoch,  g_stoch);
    cudaGetSymbolAddress((void**)&err,    g_err);
    cudaGetSymbolAddress((void**)&bvout,  g_bvout);
    cudaGetSymbolAddress((void**)&Wgt_in, g_Wgt_in);
    cudaGetSymbolAddress((void**)&Wgt_h,  g_Wgt_h);
    cudaGetSymbolAddress((void**)&Wgt_out,g_Wgt_out);
    cudaGetSymbolAddress((void**)&Wvt_out,g_Wvt_out);
    cudaGetSymbolAddress((void**)&Wvt_in, g_Wvt_in);
    cudaGetSymbolAddress((void**)&Wvt_h,  g_Wvt_h);

    float* Sbuf0 = Sb;
    float* Sbuf1 = Sb + (size_t)BSZ * DIMN;
    float* hA = hd;
    float* hB = hd + (size_t)2 * BSZ * WH;
    float* Cv = Cbuf + (size_t)BSZ * DIMN;     // v-half of gradv output

    // launch 0: weight transposes
    wtrans_all<<<512, 256>>>(Wg_in, Wv_in, Wg_h, Wv_h, Wg_out, Wv_out, bv_out);

    // launch 1: volpre = dW @ V^T (B operand is V itself, [N,K] K-major)
    {
        dim3 grid(1, (NSTEP * BSZ) / 128);
        gemm_mma<<<grid, 256, DYN_SMEM>>>(dW, Vm, Vm, nullptr, nullptr,
                                          nullptr, nullptr, nullptr, 0,
                                          volpre, DIMN, DIMN, 0, 1 << 30, 0);
    }

    auto dual_trunk = [&](const float* S, int tIdx) {
        dim3 grid(2, 128);
        gemm_mma<<<grid, 256, DYN_SMEM>>>(S, Wgt_in, Wvt_in, bg_in, bv_in,
                                          Wg_in, Wv_in, tg, tIdx,
                                          hA, WH, DIMN, 1, 64, 1);
        gemm_mma<<<grid, 256, DYN_SMEM>>>(hA, Wgt_h, Wvt_h, bg_h, bv_h,
                                          nullptr, nullptr, nullptr, 0,
                                          hB, WH, WH, 1, 64, 0);
        gemm_mma<<<grid, 256, DYN_SMEM>>>(hB, Wgt_h + 65536, Wvt_h + 65536,
                                          bg_h + WH, bv_h + WH,
                                          nullptr, nullptr, nullptr, 0,
                                          hA, WH, WH, 1, 64, 0);
        gemm_mma<<<grid, 256, DYN_SMEM>>>(hA, Wgt_h + 2 * 65536, Wvt_h + 2 * 65536,
                                          bg_h + 2 * WH, bv_h + 2 * WH,
                                          nullptr, nullptr, nullptr, 0,
                                          hB, WH, WH, 1, 64, 0);
    };
    auto gradv = [&]() {   // grad rows 0..8191 (g out-weights), v rows 8192.. (v out col 0)
        dim3 grid(1, 128);
        gemm_mma<<<grid, 256, DYN_SMEM>>>(hB, Wgt_out, Wvt_out, bg_out, bvout,
                                          nullptr, nullptr, nullptr, 0,
                                          Cbuf, DIMN, WH, 0, 64, 0);
    };

    // launches 2-5: dual trunk on [t0, S0] (launch 5 = hidden dual GEMM for ncu)
    dual_trunk(S0, 0);
    gradv();                                      // grad_0, v_0
    cudaMemsetAsync(err, 0, BSZ * sizeof(float));

    const float* Scur = S0;
    int sflip = 0;
    for (int i = 0; i < NSTEP; ++i) {
        float* Snew = sflip ? Sbuf1 : Sbuf0;
        step_err<<<BSZ / 8, 256>>>(Scur, volpre + (size_t)i * BSZ * DIMN,
                                   Cbuf, Cv, tg, i, Snew, stoch, vsave, err);
        dual_trunk(Snew, i + 1);
        gradv();                                  // grad_{i+1}, v_{i+1}
        Scur = Snew; sflip ^= 1;
    }

    // output: [v_f | S_f | error] (final error term folded in)
    pack_kernel<<<(BSZ * DIMN) / 256, 256>>>(Cv, Scur, vsave, stoch, tg, err,
                                             (float*)d_out);
}